// round 15
// baseline (speedup 1.0000x reference)
#include <cuda_runtime.h>
#include <cuda_fp16.h>
#include <cstdint>

#define H_DIM 2048
#define B_DIM 4096
#define A_DIM 5
#define T_STEPS 10

// ---------------- device scratch (no allocation allowed) ----------------
__device__ __align__(256) __half g_xh[B_DIM * H_DIM];      // x fp16       (16 MB)
__device__ __align__(256) __half g_Winh[H_DIM * H_DIM];    // W_in fp16    ( 8 MB)
__device__ __align__(256) __half g_WsnnT[H_DIM * H_DIM];   // W_snn^T fp16 ( 8 MB)
__device__ __align__(256) __half g_WcT[H_DIM * H_DIM];     // Wc^T fp16    ( 8 MB)
__device__ float g_pre_part[16][B_DIM * A_DIM];            // head partials
__device__ float g_bp_part[32][H_DIM];                     // bias partials (64-m chunks)
__device__ int g_cnt_g1[16];    // WcT 128-row stripes (16 blocks each)
__device__ int g_cnt_x[32];     // xh 128-row groups (4 blocks each)
__device__ int g_cnt_done[32];  // GEMM2 row-group completion tickets (16 each)

// ---------------- helpers ----------------
__device__ __forceinline__ uint32_t smem_u32(const void* p) {
    return (uint32_t)__cvta_generic_to_shared(p);
}
__device__ __forceinline__ void cp_async16(uint32_t dst, const void* src) {
    asm volatile("cp.async.cg.shared.global [%0], [%1], 16;" :: "r"(dst), "l"(src));
}
__device__ __forceinline__ void cp_commit() {
    asm volatile("cp.async.commit_group;");
}
template <int N>
__device__ __forceinline__ void cp_wait() {
    asm volatile("cp.async.wait_group %0;" :: "n"(N));
}
__device__ __forceinline__ void ldm_x4(uint32_t* r, uint32_t addr) {
    asm volatile("ldmatrix.sync.aligned.m8n8.x4.shared.b16 {%0,%1,%2,%3}, [%4];"
                 : "=r"(r[0]), "=r"(r[1]), "=r"(r[2]), "=r"(r[3]) : "r"(addr));
}
__device__ __forceinline__ void mma_f16(uint32_t* c, const uint32_t* a, const uint32_t* b) {
    asm volatile(
        "mma.sync.aligned.m16n8k16.row.col.f16.f16.f16.f16 "
        "{%0,%1}, {%2,%3,%4,%5}, {%6,%7}, {%0,%1};"
        : "+r"(c[0]), "+r"(c[1])
        : "r"(a[0]), "r"(a[1]), "r"(a[2]), "r"(a[3]), "r"(b[0]), "r"(b[1]));
}

__device__ __forceinline__ float lif_rate(float c) {
    float v = 0.f, cnt = 0.f;
#pragma unroll
    for (int t = 0; t < T_STEPS; t++) {
        v = v + (c - v) * 0.5f;
        if (v >= 1.0f) { cnt += 1.0f; v = 0.0f; }
    }
    return cnt * 0.1f;
}

__device__ __forceinline__ void spin_on(volatile int* c, int target) {
    while (*c < target) __nanosleep(128);
}

#define BK 32
#define SPAD 40                          // padded row stride (80 B)
#define ARR_ELE (128 * SPAD)             // halves per A (or B) tile
#define STG_ELE (2 * ARR_ELE)
#define GEMM_SMEM (4 * STG_ELE * (int)sizeof(__half))     // 81920 B

// ---------------- R8 fp16 HMMA GEMM body: D[128,128] = A @ B^T, fp16 acc.
// EPI=0: store fp16 D.
// EPI=1: LIF + head partials; bias = b_snn + sum(g_bp_part); finisher ticket
//        folds head_finish: 16th block of a row group writes final out.
template <int EPI>
__device__ __forceinline__ void gemm_body(
    const __half* __restrict__ A, const __half* __restrict__ B,
    __half* __restrict__ Cv, const float* __restrict__ bias,
    const float* __restrict__ Wout, float* __restrict__ pre_part,
    const float* __restrict__ b_out, float* __restrict__ out,
    int bxi, int bm, int bn, int N, int K, __half* sm)
{
    const int tid = threadIdx.x;
    const int wid = tid >> 5;
    const int lane = tid & 31;
    const int wm = (wid >> 1) * 32;
    const int wn = (wid & 1) * 64;

    uint32_t acc[2][8][2];
#pragma unroll
    for (int mi = 0; mi < 2; mi++)
#pragma unroll
        for (int ni = 0; ni < 8; ni++) { acc[mi][ni][0] = 0u; acc[mi][ni][1] = 0u; }

    uint32_t af[2][2][4];
    uint32_t bfr[2][4][4];

    auto stage = [&](int k0, int st) {
        __half* sA = sm + st * STG_ELE;
        __half* sB = sA + ARR_ELE;
#pragma unroll
        for (int i = 0; i < 2; i++) {
            int id = tid + i * 256;
            int r = id >> 2, c = (id & 3) * 8;
            cp_async16(smem_u32(sA + r * SPAD + c), A + (size_t)(bm + r) * K + k0 + c);
            cp_async16(smem_u32(sB + r * SPAD + c), B + (size_t)(bn + r) * K + k0 + c);
        }
        cp_commit();
    };
    auto load_frags = [&](int set, const __half* sA, const __half* sB, int ks) {
#pragma unroll
        for (int mi = 0; mi < 2; mi++)
            ldm_x4(af[set][mi], smem_u32(sA + (wm + mi * 16 + (lane & 15)) * SPAD
                                            + ks * 16 + (lane >> 4) * 8));
#pragma unroll
        for (int np = 0; np < 4; np++) {
            int rrow = wn + np * 16 + (lane & 7) + ((lane >> 4) << 3);
            int rcol = ks * 16 + (((lane >> 3) & 1) << 3);
            ldm_x4(bfr[set][np], smem_u32(sB + rrow * SPAD + rcol));
        }
    };
    auto mma_set = [&](int set) {
#pragma unroll
        for (int mi = 0; mi < 2; mi++)
#pragma unroll
            for (int ni = 0; ni < 8; ni++)
                mma_f16(acc[mi][ni], af[set][mi], &bfr[set][ni >> 1][(ni & 1) * 2]);
    };

    const int NS = K / BK;    // 64 slabs, 2 k-steps each
    stage(0, 0); stage(BK, 1); stage(2 * BK, 2);
    cp_wait<2>();
    __syncthreads();
    load_frags(0, sm, sm + ARR_ELE, 0);

    for (int s = 0; s < NS; s++) {
        const int cb = s & 3;
        const __half* sA = sm + cb * STG_ELE;
        const __half* sB = sA + ARR_ELE;
        load_frags(1, sA, sB, 1);
        mma_set(0);
        if (s + 3 < NS) { stage((s + 3) * BK, (s + 3) & 3); cp_wait<2>(); }
        else            { cp_wait<0>(); }
        __syncthreads();
        if (s + 1 < NS) {
            const int nb = (s + 1) & 3;
            load_frags(0, sm + nb * STG_ELE, sm + nb * STG_ELE + ARR_ELE, 0);
        }
        mma_set(1);
    }
    __syncthreads();

    const int gr = lane >> 2;
    const int gc = (lane & 3) * 2;

    if (EPI == 0) {
#pragma unroll
        for (int mi = 0; mi < 2; mi++) {
#pragma unroll
            for (int ni = 0; ni < 8; ni++) {
                int col = bn + wn + ni * 8 + gc;
                int row0 = bm + wm + mi * 16 + gr;
                *(uint32_t*)&Cv[(size_t)row0 * N + col] = acc[mi][ni][0];
                *(uint32_t*)&Cv[(size_t)(row0 + 8) * N + col] = acc[mi][ni][1];
            }
        }
    } else {
        float* sW = (float*)sm;
        float* sbp = sW + 128 * A_DIM;
        float* sAcc = sbp + 128;
        int* sFlag = (int*)(sAcc + 128 * A_DIM);
        for (int i = tid; i < 128 * A_DIM; i += 256) {
            int c = i / A_DIM, a = i % A_DIM;
            sW[i] = Wout[(size_t)(bn + c) * A_DIM + a];
        }
        for (int i = tid; i < 128; i += 256) {
            float r = bias[bn + i];                 // b_snn
#pragma unroll 8
            for (int p = 0; p < 32; p++) r += g_bp_part[p][bn + i];
            sbp[i] = r;
        }
        __syncthreads();

        float pr[2][2][A_DIM];
#pragma unroll
        for (int mi = 0; mi < 2; mi++) {
#pragma unroll
            for (int h = 0; h < 2; h++) {
                float p[A_DIM];
#pragma unroll
                for (int a = 0; a < A_DIM; a++) p[a] = 0.f;
#pragma unroll
                for (int ni = 0; ni < 8; ni++) {
                    int cl = wn + ni * 8 + gc;
                    float2 cf = __half22float2(*(half2*)&acc[mi][ni][h]);
                    float v0 = lif_rate(cf.x + sbp[cl]);
                    float v1 = lif_rate(cf.y + sbp[cl + 1]);
#pragma unroll
                    for (int a = 0; a < A_DIM; a++)
                        p[a] = fmaf(v0, sW[cl * A_DIM + a],
                                    fmaf(v1, sW[(cl + 1) * A_DIM + a], p[a]));
                }
#pragma unroll
                for (int a = 0; a < A_DIM; a++) {
                    p[a] += __shfl_xor_sync(0xffffffffu, p[a], 1);
                    p[a] += __shfl_xor_sync(0xffffffffu, p[a], 2);
                    pr[mi][h][a] = p[a];
                }
            }
        }
        if (wn == 64 && (lane & 3) == 0) {
#pragma unroll
            for (int mi = 0; mi < 2; mi++)
#pragma unroll
                for (int h = 0; h < 2; h++) {
                    int rl = wm + mi * 16 + h * 8 + gr;
#pragma unroll
                    for (int a = 0; a < A_DIM; a++) sAcc[rl * A_DIM + a] = pr[mi][h][a];
                }
        }
        __syncthreads();
        if (wn == 0 && (lane & 3) == 0) {
#pragma unroll
            for (int mi = 0; mi < 2; mi++)
#pragma unroll
                for (int h = 0; h < 2; h++) {
                    int rl = wm + mi * 16 + h * 8 + gr;
#pragma unroll
                    for (int a = 0; a < A_DIM; a++)
                        pre_part[(size_t)bxi * (B_DIM * A_DIM)
                                 + (size_t)(bm + rl) * A_DIM + a] =
                            pr[mi][h][a] + sAcc[rl * A_DIM + a];
                }
        }
        // ---- finisher ticket: 16th bx block for this bm writes final out ----
        __syncthreads();
        __threadfence();
        if (tid == 0) {
            int old = atomicAdd(&g_cnt_done[bm >> 7], 1);
            *sFlag = (old == 15);
        }
        __syncthreads();
        if (*sFlag) {
            __threadfence();
            for (int i = tid; i < 128 * A_DIM; i += 256) {
                int r = i / A_DIM, a = i - r * A_DIM;
                size_t off = (size_t)(bm + r) * A_DIM + a;
                float acc2 = b_out[a];
#pragma unroll
                for (int p = 0; p < 16; p++)
                    acc2 += __ldcg(&pre_part[(size_t)p * (B_DIM * A_DIM) + off]);
                float v = acc2 * 0.5f;
                out[off] = (v - 1.0f >= 0.f) ? 1.f : 0.f;
            }
        }
    }
}

// ---------------- prologue kernel (high occupancy) ----------------
// bid 0..63    : W_in rows [b*32, b*32+32) -> fp16 (bid 0 also zeroes counters)
// bid 64..2111 : transpose tile: b=bid-64, jg=b&63, mg=b>>6
//                32 j's (j0=jg*32) x 64 m's (m0=mg*64);
//                WsnnT[j, m] = f16(W_snn[m, j]) (half2 stores);
//                bp partial -> g_bp_part[mg][j]
__global__ void __launch_bounds__(256) prologue_kernel(
    const float* __restrict__ W_in, const float* __restrict__ W_snn,
    const float* __restrict__ b_in)
{
    __shared__ float t[64][33];
    const int bid = blockIdx.x;
    const int tid = threadIdx.x;

    if (bid < 64) {
        if (bid == 0) {
            if (tid < 16) g_cnt_g1[tid] = 0;
            if (tid < 32) { g_cnt_x[tid] = 0; g_cnt_done[tid] = 0; }
        }
        const float4* in4 = (const float4*)W_in;
        uint2* out4 = (uint2*)g_Winh;
        const int base = bid * 16384;
        for (int i = tid; i < 16384; i += 256) {
            float4 v = in4[base + i];
            half2 lo = __floats2half2_rn(v.x, v.y);
            half2 hi = __floats2half2_rn(v.z, v.w);
            uint2 o;
            o.x = *reinterpret_cast<unsigned int*>(&lo);
            o.y = *reinterpret_cast<unsigned int*>(&hi);
            out4[base + i] = o;
        }
    } else {
        const int b = bid - 64;
        const int j0 = (b & 63) * 32;
        const int m0 = (b >> 6) * 64;
        const int tx = tid & 31, ty = tid >> 5;   // 32 x 8
        // load 64 m-rows x 32 j-cols (coalesced 128B rows), MLP=8
#pragma unroll
        for (int i = 0; i < 8; i++)
            t[ty + i * 8][tx] = W_snn[(size_t)(m0 + ty + i * 8) * H_DIM + j0 + tx];
        __syncthreads();
        // store transposed: 32 j-rows x 64 m-cols as half2 (128B rows)
#pragma unroll
        for (int i = 0; i < 4; i++) {
            int r = ty + i * 8;                    // j_local
            half2 h = __floats2half2_rn(t[2 * tx][r], t[2 * tx + 1][r]);
            *(unsigned int*)&g_WsnnT[(size_t)(j0 + r) * H_DIM + m0 + 2 * tx] =
                *reinterpret_cast<unsigned int*>(&h);
        }
        // bp partial over the 64 m's
        float bpacc = 0.f;
#pragma unroll
        for (int i = 0; i < 8; i++)
            bpacc = fmaf(b_in[m0 + ty + i * 8], t[ty + i * 8][tx], bpacc);
        __syncthreads();
        float* red = &t[0][0];                     // reuse as [8][33]
        red[ty * 33 + tx] = bpacc;
        __syncthreads();
        if (ty == 0) {
            float r = 0.f;
#pragma unroll
            for (int p = 0; p < 8; p++) r += red[p * 33 + tx];
            g_bp_part[b >> 6][j0 + tx] = r;
        }
    }
}

// ---------------- mega kernel: GEMM1 + conv-x + GEMM2(+head finisher) --------
// bids [0,256)   : GEMM1 (bx=bid&15, by=bid>>4)   -> cnt_g1[by]
// bids [256,384) : conv-x block c                  -> cnt_x[c>>2]
// bids [384,896) : GEMM2; spins cnt_g1[bx]>=16, cnt_x[by]>=4
__global__ void __launch_bounds__(256, 2) mega_kernel(
    const float* __restrict__ x, const float* __restrict__ b_snn,
    const float* __restrict__ Wout, const float* __restrict__ b_out,
    float* __restrict__ out)
{
    extern __shared__ __half sm[];
    const int bid = blockIdx.x;
    const int tid = threadIdx.x;

    if (bid < 256) {
        const int bx = bid & 15, by = bid >> 4;
        gemm_body<0>(g_WsnnT, g_Winh, g_WcT, nullptr, nullptr, nullptr,
                     nullptr, nullptr, bx, by * 128, bx * 128, H_DIM, H_DIM, sm);
        __threadfence();
        __syncthreads();
        if (tid == 0) atomicAdd(&g_cnt_g1[by], 1);
    } else if (bid < 384) {
        const int c = bid - 256;
        const float4* in4 = (const float4*)x;
        uint2* out4 = (uint2*)g_xh;
        const int base = c * 16384;
        for (int i = tid; i < 16384; i += 256) {
            float4 v = in4[base + i];
            half2 lo = __floats2half2_rn(v.x, v.y);
            half2 hi = __floats2half2_rn(v.z, v.w);
            uint2 o;
            o.x = *reinterpret_cast<unsigned int*>(&lo);
            o.y = *reinterpret_cast<unsigned int*>(&hi);
            out4[base + i] = o;
        }
        __threadfence();
        __syncthreads();
        if (tid == 0) atomicAdd(&g_cnt_x[c >> 2], 1);
    } else {
        const int g = bid - 384;
        const int bx = g & 15, by = g >> 4;
        if (tid == 0) {
            spin_on(g_cnt_g1 + bx, 16);
            spin_on(g_cnt_x + by, 4);
        }
        __syncthreads();
        __threadfence();
        gemm_body<1>(g_xh, g_WcT, nullptr, b_snn, Wout, &g_pre_part[0][0],
                     b_out, out, bx, by * 128, bx * 128, H_DIM, H_DIM, sm);
    }
}

// ---------------- launch ----------------
extern "C" void kernel_launch(void* const* d_in, const int* in_sizes, int n_in,
                              void* d_out, int out_size) {
    const float* x     = (const float*)d_in[0];
    const float* W_in  = (const float*)d_in[1];
    const float* b_in  = (const float*)d_in[2];
    const float* W_snn = (const float*)d_in[3];
    const float* b_snn = (const float*)d_in[4];
    const float* W_out = (const float*)d_in[5];
    const float* b_out = (const float*)d_in[6];
    float* out = (float*)d_out;

    cudaFuncSetAttribute(mega_kernel, cudaFuncAttributeMaxDynamicSharedMemorySize, GEMM_SMEM);

    // (1) wide prologue: counter reset + W_in conv + W_snn^T conv + bp partials
    prologue_kernel<<<2112, 256>>>(W_in, W_snn, b_in);
    // (2) mega: GEMM1 + conv-x + GEMM2 (LIF + head partials + head finisher)
    mega_kernel<<<896, 256, GEMM_SMEM>>>(x, b_snn, W_out, b_out, out);
}

// round 16
// speedup vs baseline: 1.0209x; 1.0209x over previous
#include <cuda_runtime.h>
#include <cuda_fp16.h>
#include <cstdint>

#define H_DIM 2048
#define B_DIM 4096
#define A_DIM 5
#define T_STEPS 10

// ---------------- device scratch (no allocation allowed) ----------------
__device__ __align__(256) __half g_xh[B_DIM * H_DIM];      // x fp16       (16 MB)
__device__ __align__(256) __half g_Winh[H_DIM * H_DIM];    // W_in fp16    ( 8 MB)
__device__ __align__(256) __half g_WsnnT[H_DIM * H_DIM];   // W_snn^T fp16 ( 8 MB)
__device__ __align__(256) __half g_WcT[H_DIM * H_DIM];     // Wc^T fp16    ( 8 MB)
__device__ float g_pre_part[16][B_DIM * A_DIM];            // head partials
__device__ float g_bp_part[32][H_DIM];                     // bias partials (64-m chunks)
__device__ int g_cnt_g1[16];   // WcT 128-row stripes (16 blocks each)
__device__ int g_cnt_x[32];    // xh 128-row groups (4 blocks each)

// ---------------- helpers ----------------
__device__ __forceinline__ uint32_t smem_u32(const void* p) {
    return (uint32_t)__cvta_generic_to_shared(p);
}
__device__ __forceinline__ void cp_async16(uint32_t dst, const void* src) {
    asm volatile("cp.async.cg.shared.global [%0], [%1], 16;" :: "r"(dst), "l"(src));
}
__device__ __forceinline__ void cp_commit() {
    asm volatile("cp.async.commit_group;");
}
template <int N>
__device__ __forceinline__ void cp_wait() {
    asm volatile("cp.async.wait_group %0;" :: "n"(N));
}
__device__ __forceinline__ void ldm_x4(uint32_t* r, uint32_t addr) {
    asm volatile("ldmatrix.sync.aligned.m8n8.x4.shared.b16 {%0,%1,%2,%3}, [%4];"
                 : "=r"(r[0]), "=r"(r[1]), "=r"(r[2]), "=r"(r[3]) : "r"(addr));
}
__device__ __forceinline__ void mma_f16(uint32_t* c, const uint32_t* a, const uint32_t* b) {
    asm volatile(
        "mma.sync.aligned.m16n8k16.row.col.f16.f16.f16.f16 "
        "{%0,%1}, {%2,%3,%4,%5}, {%6,%7}, {%0,%1};"
        : "+r"(c[0]), "+r"(c[1])
        : "r"(a[0]), "r"(a[1]), "r"(a[2]), "r"(a[3]), "r"(b[0]), "r"(b[1]));
}

__device__ __forceinline__ float lif_rate(float c) {
    float v = 0.f, cnt = 0.f;
#pragma unroll
    for (int t = 0; t < T_STEPS; t++) {
        v = v + (c - v) * 0.5f;
        if (v >= 1.0f) { cnt += 1.0f; v = 0.0f; }
    }
    return cnt * 0.1f;
}

__device__ __forceinline__ void spin_on(volatile int* c, int target) {
    while (*c < target) __nanosleep(128);
}

#define BK 32
#define SPAD 40                          // padded row stride (80 B)
#define ARR_ELE (128 * SPAD)             // halves per A (or B) tile
#define STG_ELE (2 * ARR_ELE)
#define GEMM_SMEM (4 * STG_ELE * (int)sizeof(__half))     // 81920 B

// ---------------- R8 fp16 HMMA GEMM body: D[128,128] = A @ B^T, fp16 acc.
// 8 warps (4M x 2N), warp tile 32x64, 4-stage cp.async + cross-ks frag dbuf.
// EPI=0: store fp16 D.  EPI=1: LIF + head partials; bias = b_snn + sum(bp_part).
template <int EPI>
__device__ __forceinline__ void gemm_body(
    const __half* __restrict__ A, const __half* __restrict__ B,
    __half* __restrict__ Cv, const float* __restrict__ bias,
    const float* __restrict__ Wout, float* __restrict__ pre_part,
    int bxi, int bm, int bn, int N, int K, __half* sm)
{
    const int tid = threadIdx.x;
    const int wid = tid >> 5;
    const int lane = tid & 31;
    const int wm = (wid >> 1) * 32;
    const int wn = (wid & 1) * 64;

    uint32_t acc[2][8][2];
#pragma unroll
    for (int mi = 0; mi < 2; mi++)
#pragma unroll
        for (int ni = 0; ni < 8; ni++) { acc[mi][ni][0] = 0u; acc[mi][ni][1] = 0u; }

    uint32_t af[2][2][4];
    uint32_t bfr[2][4][4];

    auto stage = [&](int k0, int st) {
        __half* sA = sm + st * STG_ELE;
        __half* sB = sA + ARR_ELE;
#pragma unroll
        for (int i = 0; i < 2; i++) {
            int id = tid + i * 256;
            int r = id >> 2, c = (id & 3) * 8;
            cp_async16(smem_u32(sA + r * SPAD + c), A + (size_t)(bm + r) * K + k0 + c);
            cp_async16(smem_u32(sB + r * SPAD + c), B + (size_t)(bn + r) * K + k0 + c);
        }
        cp_commit();
    };
    auto load_frags = [&](int set, const __half* sA, const __half* sB, int ks) {
#pragma unroll
        for (int mi = 0; mi < 2; mi++)
            ldm_x4(af[set][mi], smem_u32(sA + (wm + mi * 16 + (lane & 15)) * SPAD
                                            + ks * 16 + (lane >> 4) * 8));
#pragma unroll
        for (int np = 0; np < 4; np++) {
            int rrow = wn + np * 16 + (lane & 7) + ((lane >> 4) << 3);
            int rcol = ks * 16 + (((lane >> 3) & 1) << 3);
            ldm_x4(bfr[set][np], smem_u32(sB + rrow * SPAD + rcol));
        }
    };
    auto mma_set = [&](int set) {
#pragma unroll
        for (int mi = 0; mi < 2; mi++)
#pragma unroll
            for (int ni = 0; ni < 8; ni++)
                mma_f16(acc[mi][ni], af[set][mi], &bfr[set][ni >> 1][(ni & 1) * 2]);
    };

    const int NS = K / BK;    // 64 slabs, 2 k-steps each
    stage(0, 0); stage(BK, 1); stage(2 * BK, 2);
    cp_wait<2>();
    __syncthreads();
    load_frags(0, sm, sm + ARR_ELE, 0);

    for (int s = 0; s < NS; s++) {
        const int cb = s & 3;
        const __half* sA = sm + cb * STG_ELE;
        const __half* sB = sA + ARR_ELE;
        load_frags(1, sA, sB, 1);
        mma_set(0);
        if (s + 3 < NS) { stage((s + 3) * BK, (s + 3) & 3); cp_wait<2>(); }
        else            { cp_wait<0>(); }
        __syncthreads();
        if (s + 1 < NS) {
            const int nb = (s + 1) & 3;
            load_frags(0, sm + nb * STG_ELE, sm + nb * STG_ELE + ARR_ELE, 0);
        }
        mma_set(1);
    }
    __syncthreads();

    const int gr = lane >> 2;
    const int gc = (lane & 3) * 2;

    if (EPI == 0) {
#pragma unroll
        for (int mi = 0; mi < 2; mi++) {
#pragma unroll
            for (int ni = 0; ni < 8; ni++) {
                int col = bn + wn + ni * 8 + gc;
                int row0 = bm + wm + mi * 16 + gr;
                *(uint32_t*)&Cv[(size_t)row0 * N + col] = acc[mi][ni][0];
                *(uint32_t*)&Cv[(size_t)(row0 + 8) * N + col] = acc[mi][ni][1];
            }
        }
    } else {
        float* sW = (float*)sm;
        float* sbp = sW + 128 * A_DIM;
        float* sAcc = sbp + 128;
        for (int i = tid; i < 128 * A_DIM; i += 256) {
            int c = i / A_DIM, a = i % A_DIM;
            sW[i] = Wout[(size_t)(bn + c) * A_DIM + a];
        }
        for (int i = tid; i < 128; i += 256) {
            float r = bias[bn + i];                 // b_snn
#pragma unroll 8
            for (int p = 0; p < 32; p++) r += g_bp_part[p][bn + i];
            sbp[i] = r;
        }
        __syncthreads();

        float pr[2][2][A_DIM];
#pragma unroll
        for (int mi = 0; mi < 2; mi++) {
#pragma unroll
            for (int h = 0; h < 2; h++) {
                float p[A_DIM];
#pragma unroll
                for (int a = 0; a < A_DIM; a++) p[a] = 0.f;
#pragma unroll
                for (int ni = 0; ni < 8; ni++) {
                    int cl = wn + ni * 8 + gc;
                    float2 cf = __half22float2(*(half2*)&acc[mi][ni][h]);
                    float v0 = lif_rate(cf.x + sbp[cl]);
                    float v1 = lif_rate(cf.y + sbp[cl + 1]);
#pragma unroll
                    for (int a = 0; a < A_DIM; a++)
                        p[a] = fmaf(v0, sW[cl * A_DIM + a],
                                    fmaf(v1, sW[(cl + 1) * A_DIM + a], p[a]));
                }
#pragma unroll
                for (int a = 0; a < A_DIM; a++) {
                    p[a] += __shfl_xor_sync(0xffffffffu, p[a], 1);
                    p[a] += __shfl_xor_sync(0xffffffffu, p[a], 2);
                    pr[mi][h][a] = p[a];
                }
            }
        }
        if (wn == 64 && (lane & 3) == 0) {
#pragma unroll
            for (int mi = 0; mi < 2; mi++)
#pragma unroll
                for (int h = 0; h < 2; h++) {
                    int rl = wm + mi * 16 + h * 8 + gr;
#pragma unroll
                    for (int a = 0; a < A_DIM; a++) sAcc[rl * A_DIM + a] = pr[mi][h][a];
                }
        }
        __syncthreads();
        if (wn == 0 && (lane & 3) == 0) {
#pragma unroll
            for (int mi = 0; mi < 2; mi++)
#pragma unroll
                for (int h = 0; h < 2; h++) {
                    int rl = wm + mi * 16 + h * 8 + gr;
#pragma unroll
                    for (int a = 0; a < A_DIM; a++)
                        pre_part[(size_t)bxi * (B_DIM * A_DIM)
                                 + (size_t)(bm + rl) * A_DIM + a] =
                            pr[mi][h][a] + sAcc[rl * A_DIM + a];
                }
        }
    }
}

// ---------------- prologue kernel (high occupancy, improved ILP) ----------------
// bid 0..63    : W_in rows [b*32, b*32+32) -> fp16 (bid 0 also zeroes counters)
// bid 64..2111 : transpose tile: b=bid-64, jg=b&63, mg=b>>6
//                32 j's (j0=jg*32) x 64 m's (m0=mg*64);
//                WsnnT[j, m] = f16(W_snn[m, j]) (half2 stores);
//                bp partial -> g_bp_part[mg][j]
__global__ void __launch_bounds__(256) prologue_kernel(
    const float* __restrict__ W_in, const float* __restrict__ W_snn,
    const float* __restrict__ b_in)
{
    __shared__ float t[64][33];
    const int bid = blockIdx.x;
    const int tid = threadIdx.x;

    if (bid < 64) {
        if (bid == 0) {
            if (tid < 16) g_cnt_g1[tid] = 0;
            if (tid < 32) g_cnt_x[tid] = 0;
        }
        const float4* in4 = (const float4*)W_in;
        uint2* out4 = (uint2*)g_Winh;
        const int base = bid * 16384;
        for (int i = tid; i < 16384; i += 256) {
            float4 v = in4[base + i];
            half2 lo = __floats2half2_rn(v.x, v.y);
            half2 hi = __floats2half2_rn(v.z, v.w);
            uint2 o;
            o.x = *reinterpret_cast<unsigned int*>(&lo);
            o.y = *reinterpret_cast<unsigned int*>(&hi);
            out4[base + i] = o;
        }
    } else {
        const int b = bid - 64;
        const int j0 = (b & 63) * 32;
        const int m0 = (b >> 6) * 64;
        const int tx = tid & 31, ty = tid >> 5;   // 32 x 8
        // load 64 m-rows x 32 j-cols (coalesced 128B rows), MLP=8
#pragma unroll
        for (int i = 0; i < 8; i++)
            t[ty + i * 8][tx] = W_snn[(size_t)(m0 + ty + i * 8) * H_DIM + j0 + tx];
        __syncthreads();
        // store transposed: 32 j-rows x 64 m-cols as half2 (128B rows)
#pragma unroll
        for (int i = 0; i < 4; i++) {
            int r = ty + i * 8;                    // j_local
            half2 h = __floats2half2_rn(t[2 * tx][r], t[2 * tx + 1][r]);
            *(unsigned int*)&g_WsnnT[(size_t)(j0 + r) * H_DIM + m0 + 2 * tx] =
                *reinterpret_cast<unsigned int*>(&h);
        }
        // bp partial over the 64 m's
        float bpacc = 0.f;
#pragma unroll
        for (int i = 0; i < 8; i++)
            bpacc = fmaf(b_in[m0 + ty + i * 8], t[ty + i * 8][tx], bpacc);
        __syncthreads();
        float* red = &t[0][0];                     // reuse as [8][33]
        red[ty * 33 + tx] = bpacc;
        __syncthreads();
        if (ty == 0) {
            float r = 0.f;
#pragma unroll
            for (int p = 0; p < 8; p++) r += red[p * 33 + tx];
            g_bp_part[b >> 6][j0 + tx] = r;
        }
    }
}

// ---------------- mega kernel (R11/R14): GEMM1 + conv-x + GEMM2 ----------------
// bids [0,256)   : GEMM1 (bx=bid&15, by=bid>>4)   -> cnt_g1[by]
// bids [256,384) : conv-x block c                  -> cnt_x[c>>2]
// bids [384,896) : GEMM2; spins cnt_g1[bx]>=16, cnt_x[by]>=4
__global__ void __launch_bounds__(256, 2) mega_kernel(
    const float* __restrict__ x,
    const float* __restrict__ b_snn, const float* __restrict__ Wout)
{
    extern __shared__ __half sm[];
    const int bid = blockIdx.x;
    const int tid = threadIdx.x;

    if (bid < 256) {
        const int bx = bid & 15, by = bid >> 4;
        gemm_body<0>(g_WsnnT, g_Winh, g_WcT, nullptr, nullptr, nullptr,
                     bx, by * 128, bx * 128, H_DIM, H_DIM, sm);
        __threadfence();
        __syncthreads();
        if (tid == 0) atomicAdd(&g_cnt_g1[by], 1);
    } else if (bid < 384) {
        const int c = bid - 256;
        const float4* in4 = (const float4*)x;
        uint2* out4 = (uint2*)g_xh;
        const int base = c * 16384;
        for (int i = tid; i < 16384; i += 256) {
            float4 v = in4[base + i];
            half2 lo = __floats2half2_rn(v.x, v.y);
            half2 hi = __floats2half2_rn(v.z, v.w);
            uint2 o;
            o.x = *reinterpret_cast<unsigned int*>(&lo);
            o.y = *reinterpret_cast<unsigned int*>(&hi);
            out4[base + i] = o;
        }
        __threadfence();
        __syncthreads();
        if (tid == 0) atomicAdd(&g_cnt_x[c >> 2], 1);
    } else {
        const int g = bid - 384;
        const int bx = g & 15, by = g >> 4;
        if (tid == 0) {
            spin_on(g_cnt_g1 + bx, 16);
            spin_on(g_cnt_x + by, 4);
        }
        __syncthreads();
        __threadfence();
        gemm_body<1>(g_xh, g_WcT, nullptr, b_snn, Wout, &g_pre_part[0][0],
                     bx, by * 128, bx * 128, H_DIM, H_DIM, sm);
    }
}

// ---------------- head finish ----------------
__global__ void head_finish_kernel(const float* __restrict__ pre_part,
                                   const float* __restrict__ b_out,
                                   float* __restrict__ out) {
    int i = blockIdx.x * 256 + threadIdx.x;
    if (i < B_DIM * A_DIM) {
        float acc = b_out[i % A_DIM];
#pragma unroll
        for (int nb = 0; nb < 16; nb++)
            acc += pre_part[(size_t)nb * (B_DIM * A_DIM) + i];
        float v = acc * 0.5f;
        out[i] = (v - 1.0f >= 0.f) ? 1.f : 0.f;
    }
}

// ---------------- launch ----------------
extern "C" void kernel_launch(void* const* d_in, const int* in_sizes, int n_in,
                              void* d_out, int out_size) {
    const float* x     = (const float*)d_in[0];
    const float* W_in  = (const float*)d_in[1];
    const float* b_in  = (const float*)d_in[2];
    const float* W_snn = (const float*)d_in[3];
    const float* b_snn = (const float*)d_in[4];
    const float* W_out = (const float*)d_in[5];
    const float* b_out = (const float*)d_in[6];
    float* out = (float*)d_out;

    float* pre_part;
    cudaGetSymbolAddress((void**)&pre_part, g_pre_part);

    cudaFuncSetAttribute(mega_kernel, cudaFuncAttributeMaxDynamicSharedMemorySize, GEMM_SMEM);

    // (1) wide prologue: counter reset + W_in conv + W_snn^T conv + bp partials
    prologue_kernel<<<2112, 256>>>(W_in, W_snn, b_in);
    // (2) mega: GEMM1 + conv-x + GEMM2 (fused LIF + head partials + bp sum)
    mega_kernel<<<896, 256, GEMM_SMEM>>>(x, b_snn, W_out);
    // (3) finish head
    head_finish_kernel<<<(B_DIM * A_DIM + 255) / 256, 256>>>(pre_part, b_out, out);
}

// round 17
// speedup vs baseline: 1.0687x; 1.0468x over previous
#include <cuda_runtime.h>
#include <cuda_fp16.h>
#include <cstdint>

#define H_DIM 2048
#define B_DIM 4096
#define A_DIM 5
#define T_STEPS 10

// ---------------- device scratch (no allocation allowed) ----------------
__device__ __align__(256) __half g_xh[B_DIM * H_DIM];      // x fp16       (16 MB)
__device__ __align__(256) __half g_Winh[H_DIM * H_DIM];    // W_in fp16    ( 8 MB)
__device__ __align__(256) __half g_WsnnT[H_DIM * H_DIM];   // W_snn^T fp16 ( 8 MB)
__device__ __align__(256) __half g_WcT[H_DIM * H_DIM];     // Wc^T fp16    ( 8 MB)
__device__ float g_pre_part[16][B_DIM * A_DIM];            // head partials
__device__ float g_bp_part[32][H_DIM];                     // bias partials (64-m chunks)
__device__ int g_cnt_g1[16];   // WcT 128-row stripes (16 blocks each)
__device__ int g_cnt_x[32];    // xh 128-row groups (4 blocks each)

// ---------------- helpers ----------------
__device__ __forceinline__ uint32_t smem_u32(const void* p) {
    return (uint32_t)__cvta_generic_to_shared(p);
}
__device__ __forceinline__ void cp_async16(uint32_t dst, const void* src) {
    asm volatile("cp.async.cg.shared.global [%0], [%1], 16;" :: "r"(dst), "l"(src));
}
__device__ __forceinline__ void cp_commit() {
    asm volatile("cp.async.commit_group;");
}
template <int N>
__device__ __forceinline__ void cp_wait() {
    asm volatile("cp.async.wait_group %0;" :: "n"(N));
}
__device__ __forceinline__ void ldm_x4(uint32_t* r, uint32_t addr) {
    asm volatile("ldmatrix.sync.aligned.m8n8.x4.shared.b16 {%0,%1,%2,%3}, [%4];"
                 : "=r"(r[0]), "=r"(r[1]), "=r"(r[2]), "=r"(r[3]) : "r"(addr));
}
__device__ __forceinline__ void mma_f16(uint32_t* c, const uint32_t* a, const uint32_t* b) {
    asm volatile(
        "mma.sync.aligned.m16n8k16.row.col.f16.f16.f16.f16 "
        "{%0,%1}, {%2,%3,%4,%5}, {%6,%7}, {%0,%1};"
        : "+r"(c[0]), "+r"(c[1])
        : "r"(a[0]), "r"(a[1]), "r"(a[2]), "r"(a[3]), "r"(b[0]), "r"(b[1]));
}

__device__ __forceinline__ float lif_rate(float c) {
    float v = 0.f, cnt = 0.f;
#pragma unroll
    for (int t = 0; t < T_STEPS; t++) {
        v = v + (c - v) * 0.5f;
        if (v >= 1.0f) { cnt += 1.0f; v = 0.0f; }
    }
    return cnt * 0.1f;
}

__device__ __forceinline__ void spin_on(volatile int* c, int target) {
    while (*c < target) __nanosleep(128);
}

#define BK 32
#define SPAD 40                          // padded row stride (80 B)
#define ARR_ELE (128 * SPAD)             // halves per A (or B) tile
#define STG_ELE (2 * ARR_ELE)
#define GEMM_SMEM (4 * STG_ELE * (int)sizeof(__half))     // 81920 B

// ---------------- R8 fp16 HMMA GEMM body: D[128,128] = A @ B^T, fp16 acc.
// 8 warps (4M x 2N), warp tile 32x64, 4-stage cp.async + cross-ks frag dbuf.
// EPI=0: store fp16 D.  EPI=1: LIF + head partials; bias = b_snn + sum(bp_part).
template <int EPI>
__device__ __forceinline__ void gemm_body(
    const __half* __restrict__ A, const __half* __restrict__ B,
    __half* __restrict__ Cv, const float* __restrict__ bias,
    const float* __restrict__ Wout, float* __restrict__ pre_part,
    int bxi, int bm, int bn, int N, int K, __half* sm)
{
    const int tid = threadIdx.x;
    const int wid = tid >> 5;
    const int lane = tid & 31;
    const int wm = (wid >> 1) * 32;
    const int wn = (wid & 1) * 64;

    uint32_t acc[2][8][2];
#pragma unroll
    for (int mi = 0; mi < 2; mi++)
#pragma unroll
        for (int ni = 0; ni < 8; ni++) { acc[mi][ni][0] = 0u; acc[mi][ni][1] = 0u; }

    uint32_t af[2][2][4];
    uint32_t bfr[2][4][4];

    auto stage = [&](int k0, int st) {
        __half* sA = sm + st * STG_ELE;
        __half* sB = sA + ARR_ELE;
#pragma unroll
        for (int i = 0; i < 2; i++) {
            int id = tid + i * 256;
            int r = id >> 2, c = (id & 3) * 8;
            cp_async16(smem_u32(sA + r * SPAD + c), A + (size_t)(bm + r) * K + k0 + c);
            cp_async16(smem_u32(sB + r * SPAD + c), B + (size_t)(bn + r) * K + k0 + c);
        }
        cp_commit();
    };
    auto load_frags = [&](int set, const __half* sA, const __half* sB, int ks) {
#pragma unroll
        for (int mi = 0; mi < 2; mi++)
            ldm_x4(af[set][mi], smem_u32(sA + (wm + mi * 16 + (lane & 15)) * SPAD
                                            + ks * 16 + (lane >> 4) * 8));
#pragma unroll
        for (int np = 0; np < 4; np++) {
            int rrow = wn + np * 16 + (lane & 7) + ((lane >> 4) << 3);
            int rcol = ks * 16 + (((lane >> 3) & 1) << 3);
            ldm_x4(bfr[set][np], smem_u32(sB + rrow * SPAD + rcol));
        }
    };
    auto mma_set = [&](int set) {
#pragma unroll
        for (int mi = 0; mi < 2; mi++)
#pragma unroll
            for (int ni = 0; ni < 8; ni++)
                mma_f16(acc[mi][ni], af[set][mi], &bfr[set][ni >> 1][(ni & 1) * 2]);
    };

    const int NS = K / BK;    // 64 slabs, 2 k-steps each
    stage(0, 0); stage(BK, 1); stage(2 * BK, 2);
    cp_wait<2>();
    __syncthreads();
    load_frags(0, sm, sm + ARR_ELE, 0);

    for (int s = 0; s < NS; s++) {
        const int cb = s & 3;
        const __half* sA = sm + cb * STG_ELE;
        const __half* sB = sA + ARR_ELE;
        load_frags(1, sA, sB, 1);
        mma_set(0);
        if (s + 3 < NS) { stage((s + 3) * BK, (s + 3) & 3); cp_wait<2>(); }
        else            { cp_wait<0>(); }
        __syncthreads();
        if (s + 1 < NS) {
            const int nb = (s + 1) & 3;
            load_frags(0, sm + nb * STG_ELE, sm + nb * STG_ELE + ARR_ELE, 0);
        }
        mma_set(1);
    }
    __syncthreads();

    const int gr = lane >> 2;
    const int gc = (lane & 3) * 2;

    if (EPI == 0) {
#pragma unroll
        for (int mi = 0; mi < 2; mi++) {
#pragma unroll
            for (int ni = 0; ni < 8; ni++) {
                int col = bn + wn + ni * 8 + gc;
                int row0 = bm + wm + mi * 16 + gr;
                *(uint32_t*)&Cv[(size_t)row0 * N + col] = acc[mi][ni][0];
                *(uint32_t*)&Cv[(size_t)(row0 + 8) * N + col] = acc[mi][ni][1];
            }
        }
    } else {
        float* sW = (float*)sm;
        float* sbp = sW + 128 * A_DIM;
        float* sAcc = sbp + 128;
        for (int i = tid; i < 128 * A_DIM; i += 256) {
            int c = i / A_DIM, a = i % A_DIM;
            sW[i] = Wout[(size_t)(bn + c) * A_DIM + a];
        }
        for (int i = tid; i < 128; i += 256) {
            float r = bias[bn + i];                 // b_snn
#pragma unroll 8
            for (int p = 0; p < 32; p++) r += g_bp_part[p][bn + i];
            sbp[i] = r;
        }
        __syncthreads();

        float pr[2][2][A_DIM];
#pragma unroll
        for (int mi = 0; mi < 2; mi++) {
#pragma unroll
            for (int h = 0; h < 2; h++) {
                float p[A_DIM];
#pragma unroll
                for (int a = 0; a < A_DIM; a++) p[a] = 0.f;
#pragma unroll
                for (int ni = 0; ni < 8; ni++) {
                    int cl = wn + ni * 8 + gc;
                    float2 cf = __half22float2(*(half2*)&acc[mi][ni][h]);
                    float v0 = lif_rate(cf.x + sbp[cl]);
                    float v1 = lif_rate(cf.y + sbp[cl + 1]);
#pragma unroll
                    for (int a = 0; a < A_DIM; a++)
                        p[a] = fmaf(v0, sW[cl * A_DIM + a],
                                    fmaf(v1, sW[(cl + 1) * A_DIM + a], p[a]));
                }
#pragma unroll
                for (int a = 0; a < A_DIM; a++) {
                    p[a] += __shfl_xor_sync(0xffffffffu, p[a], 1);
                    p[a] += __shfl_xor_sync(0xffffffffu, p[a], 2);
                    pr[mi][h][a] = p[a];
                }
            }
        }
        if (wn == 64 && (lane & 3) == 0) {
#pragma unroll
            for (int mi = 0; mi < 2; mi++)
#pragma unroll
                for (int h = 0; h < 2; h++) {
                    int rl = wm + mi * 16 + h * 8 + gr;
#pragma unroll
                    for (int a = 0; a < A_DIM; a++) sAcc[rl * A_DIM + a] = pr[mi][h][a];
                }
        }
        __syncthreads();
        if (wn == 0 && (lane & 3) == 0) {
#pragma unroll
            for (int mi = 0; mi < 2; mi++)
#pragma unroll
                for (int h = 0; h < 2; h++) {
                    int rl = wm + mi * 16 + h * 8 + gr;
#pragma unroll
                    for (int a = 0; a < A_DIM; a++)
                        pre_part[(size_t)bxi * (B_DIM * A_DIM)
                                 + (size_t)(bm + rl) * A_DIM + a] =
                            pr[mi][h][a] + sAcc[rl * A_DIM + a];
                }
        }
    }
}

// ---------------- prologue kernel (rebalanced) ----------------
// bid 0..511   : W_in conversion, 8 float4 iters each (bid 0 zeroes counters)
// bid 512..2559: transpose tile: b=bid-512, jg=b&63, mg=b>>6
//                32 j's x 64 m's; WsnnT[j,m]=f16(W_snn[m,j]); bp -> g_bp_part[mg]
__global__ void __launch_bounds__(256) prologue_kernel(
    const float* __restrict__ W_in, const float* __restrict__ W_snn,
    const float* __restrict__ b_in)
{
    __shared__ float t[64][33];
    const int bid = blockIdx.x;
    const int tid = threadIdx.x;

    if (bid < 512) {
        if (bid == 0) {
            if (tid < 16) g_cnt_g1[tid] = 0;
            if (tid < 32) g_cnt_x[tid] = 0;
        }
        const float4* in4 = (const float4*)W_in;
        uint2* out4 = (uint2*)g_Winh;
        const int base = bid * 2048;              // 2048 float4 per block
#pragma unroll
        for (int i = 0; i < 8; i++) {
            int idx = base + tid + i * 256;
            float4 v = in4[idx];
            half2 lo = __floats2half2_rn(v.x, v.y);
            half2 hi = __floats2half2_rn(v.z, v.w);
            uint2 o;
            o.x = *reinterpret_cast<unsigned int*>(&lo);
            o.y = *reinterpret_cast<unsigned int*>(&hi);
            out4[idx] = o;
        }
    } else {
        const int b = bid - 512;
        const int j0 = (b & 63) * 32;
        const int m0 = (b >> 6) * 64;
        const int tx = tid & 31, ty = tid >> 5;   // 32 x 8
#pragma unroll
        for (int i = 0; i < 8; i++)
            t[ty + i * 8][tx] = W_snn[(size_t)(m0 + ty + i * 8) * H_DIM + j0 + tx];
        __syncthreads();
#pragma unroll
        for (int i = 0; i < 4; i++) {
            int r = ty + i * 8;                    // j_local
            half2 h = __floats2half2_rn(t[2 * tx][r], t[2 * tx + 1][r]);
            *(unsigned int*)&g_WsnnT[(size_t)(j0 + r) * H_DIM + m0 + 2 * tx] =
                *reinterpret_cast<unsigned int*>(&h);
        }
        float bpacc = 0.f;
#pragma unroll
        for (int i = 0; i < 8; i++)
            bpacc = fmaf(b_in[m0 + ty + i * 8], t[ty + i * 8][tx], bpacc);
        __syncthreads();
        float* red = &t[0][0];                     // reuse as [8][33]
        red[ty * 33 + tx] = bpacc;
        __syncthreads();
        if (ty == 0) {
            float r = 0.f;
#pragma unroll
            for (int p = 0; p < 8; p++) r += red[p * 33 + tx];
            g_bp_part[b >> 6][j0 + tx] = r;
        }
    }
}

// ---------------- mega kernel: GEMM1 + conv-x + GEMM2 ----------------
// bids [0,256)   : GEMM1 (bx=bid&15, by=bid>>4)   -> cnt_g1[by]
// bids [256,384) : conv-x block c                  -> cnt_x[c>>2]
// bids [384,896) : GEMM2 (bx=g>>5, by=g&31)        spins cnt_g1[bx], cnt_x[by]
//                  (bx major order matches GEMM1 stripe completion order)
__global__ void __launch_bounds__(256, 2) mega_kernel(
    const float* __restrict__ x,
    const float* __restrict__ b_snn, const float* __restrict__ Wout)
{
    extern __shared__ __half sm[];
    const int bid = blockIdx.x;
    const int tid = threadIdx.x;

    if (bid < 256) {
        const int bx = bid & 15, by = bid >> 4;
        gemm_body<0>(g_WsnnT, g_Winh, g_WcT, nullptr, nullptr, nullptr,
                     bx, by * 128, bx * 128, H_DIM, H_DIM, sm);
        __threadfence();
        __syncthreads();
        if (tid == 0) atomicAdd(&g_cnt_g1[by], 1);
    } else if (bid < 384) {
        const int c = bid - 256;
        const float4* in4 = (const float4*)x;
        uint2* out4 = (uint2*)g_xh;
        const int base = c * 16384;
        for (int i = tid; i < 16384; i += 256) {
            float4 v = in4[base + i];
            half2 lo = __floats2half2_rn(v.x, v.y);
            half2 hi = __floats2half2_rn(v.z, v.w);
            uint2 o;
            o.x = *reinterpret_cast<unsigned int*>(&lo);
            o.y = *reinterpret_cast<unsigned int*>(&hi);
            out4[base + i] = o;
        }
        __threadfence();
        __syncthreads();
        if (tid == 0) atomicAdd(&g_cnt_x[c >> 2], 1);
    } else {
        const int g = bid - 384;
        const int bx = g >> 5, by = g & 31;   // bx-major: matches producer order
        if (tid == 0) {
            spin_on(g_cnt_g1 + bx, 16);
            spin_on(g_cnt_x + by, 4);
        }
        __syncthreads();
        __threadfence();
        gemm_body<1>(g_xh, g_WcT, nullptr, b_snn, Wout, &g_pre_part[0][0],
                     bx, by * 128, bx * 128, H_DIM, H_DIM, sm);
    }
}

// ---------------- head finish ----------------
__global__ void head_finish_kernel(const float* __restrict__ pre_part,
                                   const float* __restrict__ b_out,
                                   float* __restrict__ out) {
    int i = blockIdx.x * 256 + threadIdx.x;
    if (i < B_DIM * A_DIM) {
        float acc = b_out[i % A_DIM];
#pragma unroll
        for (int nb = 0; nb < 16; nb++)
            acc += pre_part[(size_t)nb * (B_DIM * A_DIM) + i];
        float v = acc * 0.5f;
        out[i] = (v - 1.0f >= 0.f) ? 1.f : 0.f;
    }
}

// ---------------- launch ----------------
extern "C" void kernel_launch(void* const* d_in, const int* in_sizes, int n_in,
                              void* d_out, int out_size) {
    const float* x     = (const float*)d_in[0];
    const float* W_in  = (const float*)d_in[1];
    const float* b_in  = (const float*)d_in[2];
    const float* W_snn = (const float*)d_in[3];
    const float* b_snn = (const float*)d_in[4];
    const float* W_out = (const float*)d_in[5];
    const float* b_out = (const float*)d_in[6];
    float* out = (float*)d_out;

    float* pre_part;
    cudaGetSymbolAddress((void**)&pre_part, g_pre_part);

    cudaFuncSetAttribute(mega_kernel, cudaFuncAttributeMaxDynamicSharedMemorySize, GEMM_SMEM);

    // (1) wide prologue: counter reset + W_in conv + W_snn^T conv + bp partials
    prologue_kernel<<<2560, 256>>>(W_in, W_snn, b_in);
    // (2) mega: GEMM1 + conv-x + GEMM2 (fused LIF + head partials + bp sum)
    mega_kernel<<<896, 256, GEMM_SMEM>>>(x, b_snn, W_out);
    // (3) finish head
    head_finish_kernel<<<(B_DIM * A_DIM + 255) / 256, 256>>>(pre_part, b_out, out);
}